// round 5
// baseline (speedup 1.0000x reference)
#include <cuda_runtime.h>
#include <cstdint>

// ---------------- problem constants ----------------
// B=256, D0=16, D1=32, D2=64, D_FFN=2048, F1=2048, F2=1024
// out dtype float32, out_size = 256*16*32*64 = 8388608

#define BM 128
#define BN 128
#define BK 32
#define BKP 36          // padded smem row stride (floats) -> conflict-free frags
#define STAGES 3
#define NTHREADS 256

// scratch: h1 [B, D0, 2048] (32MB), h2 [B, D1, 2048] (64MB)
__device__ __align__(128) float g_h1[256L * 16 * 2048];
__device__ __align__(128) float g_h2[256L * 32 * 2048];

static __device__ __forceinline__ uint32_t smem_u32(const void* p) {
    return (uint32_t)__cvta_generic_to_shared(p);
}
static __device__ __forceinline__ void cp_async16(uint32_t s, const void* g) {
    asm volatile("cp.async.cg.shared.global [%0], [%1], 16;\n" :: "r"(s), "l"(g));
}
static __device__ __forceinline__ void cp_commit() {
    asm volatile("cp.async.commit_group;\n" ::: "memory");
}
template <int N_>
static __device__ __forceinline__ void cp_wait() {
    asm volatile("cp.async.wait_group %0;\n" :: "n"(N_) : "memory");
}
static __device__ __forceinline__ uint32_t f2tf32(float f) {
    uint32_t u;
    asm("cvt.rna.tf32.f32 %0, %1;\n" : "=r"(u) : "f"(f));
    return u;
}
static __device__ __forceinline__ void mma_tf32(float c[4],
                                                uint32_t a0, uint32_t a1, uint32_t a2, uint32_t a3,
                                                uint32_t b0, uint32_t b1) {
    asm volatile(
        "mma.sync.aligned.m16n8k8.row.col.f32.tf32.tf32.f32 "
        "{%0,%1,%2,%3}, {%4,%5,%6,%7}, {%8,%9}, {%0,%1,%2,%3};\n"
        : "+f"(c[0]), "+f"(c[1]), "+f"(c[2]), "+f"(c[3])
        : "r"(a0), "r"(a1), "r"(a2), "r"(a3), "r"(b0), "r"(b1));
}

// Grouped TN GEMM:  C[m,n] = sum_k A_g[m,k] * W_g[n,k]
// A addressing (handles strided gather without a transpose pass):
//   A elem (m,k)  at A0 + g*a_g + m*a_ldr + (k>>6)*a_ldblk + (k&63)
// W addressing:   W0 + g*w_g + n*K + k            (always K-contiguous)
// out addressing: out0 + g*o_g + m*o_ldr + (n>>6)*o_ldblk + (n&63)
// MODE 0: out = gelu(acc + bias[n])
// MODE 1: out = aux0[same index] + 0.5f*(acc + bias[n])
template <int MODE>
__global__ void __launch_bounds__(NTHREADS)
grouped_gemm(const float* __restrict__ A0, long a_g, long a_ldr, long a_ldblk,
             const float* __restrict__ W0, long w_g,
             const float* __restrict__ bias0,
             float* __restrict__ out0, long o_g, long o_ldr, long o_ldblk,
             const float* __restrict__ aux0,
             int N, int K) {
    extern __shared__ float smem[];
    float* As = smem;                        // [STAGES][BM][BKP]
    float* Bs = smem + (long)STAGES * BM * BKP;  // [STAGES][BN][BKP]

    const int g  = blockIdx.z;
    const int bm = blockIdx.y;
    const int bn = blockIdx.x;

    const float* A    = A0 + (long)g * a_g;
    const float* W    = W0 + (long)g * w_g;
    const float* bias = bias0 + (long)g * (long)N;

    const int tid  = threadIdx.x;
    const int lrow = tid >> 3;            // 0..31 (row within a 32-row pass)
    const int lk4  = (tid & 7) * 4;       // 0,4,...,28 (k offset of 16B chunk)

    const int warp = tid >> 5;
    const int lane = tid & 31;
    const int wm   = (warp >> 2) * 64;    // warp m offset (0 / 64)
    const int wn   = (warp & 3) * 32;     // warp n offset (0/32/64/96)
    const int qrow = lane >> 2;           // 0..7
    const int qk   = lane & 3;            // 0..3

    float c[4][4][4];
#pragma unroll
    for (int mi = 0; mi < 4; mi++)
#pragma unroll
        for (int ni = 0; ni < 4; ni++)
#pragma unroll
            for (int r = 0; r < 4; r++) c[mi][ni][r] = 0.0f;

    auto load_tile = [&](int kt, int stage) {
        float* as = As + (long)stage * BM * BKP;
        float* bs = Bs + (long)stage * BN * BKP;
        const long kg   = (long)kt * BK + lk4;
        const long ablk = (kg >> 6) * a_ldblk + (kg & 63);
#pragma unroll
        for (int p = 0; p < 4; p++) {
            const int r = lrow + p * 32;
            cp_async16(smem_u32(&as[r * BKP + lk4]),
                       A + (long)(bm * BM + r) * a_ldr + ablk);
        }
#pragma unroll
        for (int p = 0; p < 4; p++) {
            const int r = lrow + p * 32;
            cp_async16(smem_u32(&bs[r * BKP + lk4]),
                       W + (long)(bn * BN + r) * K + kg);
        }
    };

    const int KT = K / BK;

    // prologue: prefetch STAGES-1 tiles
#pragma unroll
    for (int s = 0; s < STAGES - 1; s++) {
        load_tile(s, s);
        cp_commit();
    }

    for (int kt = 0; kt < KT; kt++) {
        cp_wait<STAGES - 2>();
        __syncthreads();   // also protects the stage about to be overwritten

        const int nt = kt + STAGES - 1;
        if (nt < KT) load_tile(nt, nt % STAGES);
        cp_commit();

        const float* as = As + (long)(kt % STAGES) * BM * BKP;
        const float* bs = Bs + (long)(kt % STAGES) * BN * BKP;

#pragma unroll
        for (int ks = 0; ks < BK / 8; ks++) {
            const int k0 = ks * 8 + qk;
            uint32_t af[4][4], bf[4][2];
#pragma unroll
            for (int mi = 0; mi < 4; mi++) {
                const int m = wm + mi * 16 + qrow;
                af[mi][0] = f2tf32(as[m * BKP + k0]);
                af[mi][1] = f2tf32(as[(m + 8) * BKP + k0]);
                af[mi][2] = f2tf32(as[m * BKP + k0 + 4]);
                af[mi][3] = f2tf32(as[(m + 8) * BKP + k0 + 4]);
            }
#pragma unroll
            for (int ni = 0; ni < 4; ni++) {
                const int n = wn + ni * 8 + qrow;
                bf[ni][0] = f2tf32(bs[n * BKP + k0]);
                bf[ni][1] = f2tf32(bs[n * BKP + k0 + 4]);
            }
#pragma unroll
            for (int mi = 0; mi < 4; mi++)
#pragma unroll
                for (int ni = 0; ni < 4; ni++)
                    mma_tf32(c[mi][ni], af[mi][0], af[mi][1], af[mi][2], af[mi][3],
                             bf[ni][0], bf[ni][1]);
        }
    }
    cp_wait<0>();

    // -------- epilogue --------
    const long og = (long)g * o_g;
#pragma unroll
    for (int mi = 0; mi < 4; mi++) {
        const int mrow = bm * BM + wm + mi * 16 + qrow;
#pragma unroll
        for (int ni = 0; ni < 4; ni++) {
            const int ncol = bn * BN + wn + ni * 8 + qk * 2;
#pragma unroll
            for (int rr = 0; rr < 2; rr++) {
                const long mterm = (long)(mrow + rr * 8) * o_ldr;
#pragma unroll
                for (int cc = 0; cc < 2; cc++) {
                    const int n_g = ncol + cc;
                    const float v = c[mi][ni][rr * 2 + cc] + bias[n_g];
                    const long oaddr = og + mterm + (long)(n_g >> 6) * o_ldblk + (n_g & 63);
                    if (MODE == 0) {
                        // exact-erf GELU
                        out0[oaddr] = 0.5f * v * (1.0f + erff(v * 0.70710678118654752f));
                    } else {
                        out0[oaddr] = aux0[oaddr] + 0.5f * v;
                    }
                }
            }
        }
    }
}

extern "C" void kernel_launch(void* const* d_in, const int* in_sizes, int n_in,
                              void* d_out, int out_size) {
    const float* x    = (const float*)d_in[0];
    const float* W0_1 = (const float*)d_in[1];
    const float* b0_1 = (const float*)d_in[2];
    const float* W1_1 = (const float*)d_in[3];
    const float* b1_1 = (const float*)d_in[4];
    const float* W0_2 = (const float*)d_in[5];
    const float* b0_2 = (const float*)d_in[6];
    const float* W1_2 = (const float*)d_in[7];
    const float* b1_2 = (const float*)d_in[8];
    float* out = (float*)d_out;

    void* p1 = nullptr; void* p2 = nullptr;
    cudaGetSymbolAddress(&p1, g_h1);
    cudaGetSymbolAddress(&p2, g_h2);
    float* h1 = (float*)p1;
    float* h2 = (float*)p2;

    const size_t shm = (size_t)STAGES * (BM + BN) * BKP * sizeof(float);  // 110592
    cudaFuncSetAttribute(grouped_gemm<0>, cudaFuncAttributeMaxDynamicSharedMemorySize, (int)shm);
    cudaFuncSetAttribute(grouped_gemm<1>, cudaFuncAttributeMaxDynamicSharedMemorySize, (int)shm);

    dim3 blk(NTHREADS);

    // G1a: h1[b,i,k] = gelu(x1 @ W0_1[i]^T + b0_1[i])    M=256,N=2048,K=2048, G=16
    grouped_gemm<0><<<dim3(2048 / BN, 256 / BM, 16), blk, shm>>>(
        x, 2048L, 32768L, 64L,
        W0_1, 2048L * 2048L,
        b0_1,
        h1, 2048L, 32768L, 64L,
        nullptr, 2048, 2048);

    // G2a: h2[b,j,k] = gelu(x2 @ W0_2[j]^T + b0_2[j])    M=256,N=2048,K=1024, G=32
    // A gather: x2[b, i*64+d] = x[b,i,j,d] -> base x + j*64, ldr 32768, ldblk 2048
    grouped_gemm<0><<<dim3(2048 / BN, 256 / BM, 32), blk, shm>>>(
        x, 64L, 32768L, 2048L,
        W0_2, 2048L * 1024L,
        b0_2,
        h2, 2048L, 65536L, 64L,
        nullptr, 2048, 1024);

    // G1b: out[b,i,f1] = x[b,i,f1] + 0.5*(h1 @ W1_1[i]^T + b1_1[i])   N=2048,K=2048, G=16
    grouped_gemm<1><<<dim3(2048 / BN, 256 / BM, 16), blk, shm>>>(
        h1, 2048L, 32768L, 64L,
        W1_1, 2048L * 2048L,
        b1_1,
        out, 2048L, 32768L, 64L,
        x, 2048, 2048);

    // G2b: out[b,i,j,d] += 0.5*(h2 @ W1_2[j]^T + b1_2[j])   N=1024,K=2048, G=32
    // out scatter: n=(i,d) -> base out + j*64, ldr 32768, ldblk 2048; aux = out (read-modify-write)
    grouped_gemm<1><<<dim3(1024 / BN, 256 / BM, 32), blk, shm>>>(
        h2, 2048L, 65536L, 64L,
        W1_2, 1024L * 2048L,
        b1_2,
        out, 64L, 32768L, 2048L,
        out, 1024, 2048);

    (void)in_sizes; (void)n_in; (void)out_size;
}

// round 6
// speedup vs baseline: 1.0020x; 1.0020x over previous
#include <cuda_runtime.h>
#include <cstdint>

// ---------------- problem constants ----------------
// B=256, D0=16, D1=32, D2=64, D_FFN=2048, F1=2048, F2=1024
// out dtype float32, out_size = 256*16*32*64 = 8388608

#define BM 128
#define BN 128
#define BK 32
#define BKP 36          // padded smem row stride (floats) -> conflict-free frags
#define STAGES 3
#define NTHREADS 256

// scratch: h1 [B, D0, 2048] (32MB), h2 [B, D1, 2048] (64MB)
__device__ __align__(128) float g_h1[256L * 16 * 2048];
__device__ __align__(128) float g_h2[256L * 32 * 2048];

static __device__ __forceinline__ uint32_t smem_u32(const void* p) {
    return (uint32_t)__cvta_generic_to_shared(p);
}
static __device__ __forceinline__ void cp_async16(uint32_t s, const void* g) {
    asm volatile("cp.async.cg.shared.global [%0], [%1], 16;\n" :: "r"(s), "l"(g));
}
static __device__ __forceinline__ void cp_commit() {
    asm volatile("cp.async.commit_group;\n" ::: "memory");
}
template <int N_>
static __device__ __forceinline__ void cp_wait() {
    asm volatile("cp.async.wait_group %0;\n" :: "n"(N_) : "memory");
}
static __device__ __forceinline__ uint32_t f2tf32(float f) {
    uint32_t u;
    asm("cvt.rna.tf32.f32 %0, %1;\n" : "=r"(u) : "f"(f));
    return u;
}
static __device__ __forceinline__ void mma_tf32(float c[4],
                                                uint32_t a0, uint32_t a1, uint32_t a2, uint32_t a3,
                                                uint32_t b0, uint32_t b1) {
    asm volatile(
        "mma.sync.aligned.m16n8k8.row.col.f32.tf32.tf32.f32 "
        "{%0,%1,%2,%3}, {%4,%5,%6,%7}, {%8,%9}, {%0,%1,%2,%3};\n"
        : "+f"(c[0]), "+f"(c[1]), "+f"(c[2]), "+f"(c[3])
        : "r"(a0), "r"(a1), "r"(a2), "r"(a3), "r"(b0), "r"(b1));
}

// Grouped TN GEMM:  C[m,n] = sum_k A_g[m,k] * W_g[n,k]
// A addressing (handles strided gather without a transpose pass):
//   A elem (m,k)  at A0 + g*a_g + m*a_ldr + (k>>6)*a_ldblk + (k&63)
// W addressing:   W0 + g*w_g + n*K + k            (always K-contiguous)
// out addressing: out0 + g*o_g + m*o_ldr + (n>>6)*o_ldblk + (n&63)
// MODE 0: out = gelu(acc + bias[n])
// MODE 1: out = aux0[same index] + 0.5f*(acc + bias[n])
template <int MODE>
__global__ void __launch_bounds__(NTHREADS)
grouped_gemm(const float* __restrict__ A0, long a_g, long a_ldr, long a_ldblk,
             const float* __restrict__ W0, long w_g,
             const float* __restrict__ bias0,
             float* __restrict__ out0, long o_g, long o_ldr, long o_ldblk,
             const float* __restrict__ aux0,
             int N, int K) {
    extern __shared__ float smem[];
    float* As = smem;                        // [STAGES][BM][BKP]
    float* Bs = smem + (long)STAGES * BM * BKP;  // [STAGES][BN][BKP]

    const int g  = blockIdx.z;
    const int bm = blockIdx.y;
    const int bn = blockIdx.x;

    const float* A    = A0 + (long)g * a_g;
    const float* W    = W0 + (long)g * w_g;
    const float* bias = bias0 + (long)g * (long)N;

    const int tid  = threadIdx.x;
    const int lrow = tid >> 3;            // 0..31 (row within a 32-row pass)
    const int lk4  = (tid & 7) * 4;       // 0,4,...,28 (k offset of 16B chunk)

    const int warp = tid >> 5;
    const int lane = tid & 31;
    const int wm   = (warp >> 2) * 64;    // warp m offset (0 / 64)
    const int wn   = (warp & 3) * 32;     // warp n offset (0/32/64/96)
    const int qrow = lane >> 2;           // 0..7
    const int qk   = lane & 3;            // 0..3

    float c[4][4][4];
#pragma unroll
    for (int mi = 0; mi < 4; mi++)
#pragma unroll
        for (int ni = 0; ni < 4; ni++)
#pragma unroll
            for (int r = 0; r < 4; r++) c[mi][ni][r] = 0.0f;

    auto load_tile = [&](int kt, int stage) {
        float* as = As + (long)stage * BM * BKP;
        float* bs = Bs + (long)stage * BN * BKP;
        const long kg   = (long)kt * BK + lk4;
        const long ablk = (kg >> 6) * a_ldblk + (kg & 63);
#pragma unroll
        for (int p = 0; p < 4; p++) {
            const int r = lrow + p * 32;
            cp_async16(smem_u32(&as[r * BKP + lk4]),
                       A + (long)(bm * BM + r) * a_ldr + ablk);
        }
#pragma unroll
        for (int p = 0; p < 4; p++) {
            const int r = lrow + p * 32;
            cp_async16(smem_u32(&bs[r * BKP + lk4]),
                       W + (long)(bn * BN + r) * K + kg);
        }
    };

    const int KT = K / BK;

    // prologue: prefetch STAGES-1 tiles
#pragma unroll
    for (int s = 0; s < STAGES - 1; s++) {
        load_tile(s, s);
        cp_commit();
    }

    for (int kt = 0; kt < KT; kt++) {
        cp_wait<STAGES - 2>();
        __syncthreads();   // also protects the stage about to be overwritten

        const int nt = kt + STAGES - 1;
        if (nt < KT) load_tile(nt, nt % STAGES);
        cp_commit();

        const float* as = As + (long)(kt % STAGES) * BM * BKP;
        const float* bs = Bs + (long)(kt % STAGES) * BN * BKP;

#pragma unroll
        for (int ks = 0; ks < BK / 8; ks++) {
            const int k0 = ks * 8 + qk;
            uint32_t af[4][4], bf[4][2];
#pragma unroll
            for (int mi = 0; mi < 4; mi++) {
                const int m = wm + mi * 16 + qrow;
                af[mi][0] = f2tf32(as[m * BKP + k0]);
                af[mi][1] = f2tf32(as[(m + 8) * BKP + k0]);
                af[mi][2] = f2tf32(as[m * BKP + k0 + 4]);
                af[mi][3] = f2tf32(as[(m + 8) * BKP + k0 + 4]);
            }
#pragma unroll
            for (int ni = 0; ni < 4; ni++) {
                const int n = wn + ni * 8 + qrow;
                bf[ni][0] = f2tf32(bs[n * BKP + k0]);
                bf[ni][1] = f2tf32(bs[n * BKP + k0 + 4]);
            }
#pragma unroll
            for (int mi = 0; mi < 4; mi++)
#pragma unroll
                for (int ni = 0; ni < 4; ni++)
                    mma_tf32(c[mi][ni], af[mi][0], af[mi][1], af[mi][2], af[mi][3],
                             bf[ni][0], bf[ni][1]);
        }
    }
    cp_wait<0>();

    // -------- epilogue --------
    const long og = (long)g * o_g;
#pragma unroll
    for (int mi = 0; mi < 4; mi++) {
        const int mrow = bm * BM + wm + mi * 16 + qrow;
#pragma unroll
        for (int ni = 0; ni < 4; ni++) {
            const int ncol = bn * BN + wn + ni * 8 + qk * 2;
#pragma unroll
            for (int rr = 0; rr < 2; rr++) {
                const long mterm = (long)(mrow + rr * 8) * o_ldr;
#pragma unroll
                for (int cc = 0; cc < 2; cc++) {
                    const int n_g = ncol + cc;
                    const float v = c[mi][ni][rr * 2 + cc] + bias[n_g];
                    const long oaddr = og + mterm + (long)(n_g >> 6) * o_ldblk + (n_g & 63);
                    if (MODE == 0) {
                        // exact-erf GELU
                        out0[oaddr] = 0.5f * v * (1.0f + erff(v * 0.70710678118654752f));
                    } else {
                        out0[oaddr] = aux0[oaddr] + 0.5f * v;
                    }
                }
            }
        }
    }
}

extern "C" void kernel_launch(void* const* d_in, const int* in_sizes, int n_in,
                              void* d_out, int out_size) {
    const float* x    = (const float*)d_in[0];
    const float* W0_1 = (const float*)d_in[1];
    const float* b0_1 = (const float*)d_in[2];
    const float* W1_1 = (const float*)d_in[3];
    const float* b1_1 = (const float*)d_in[4];
    const float* W0_2 = (const float*)d_in[5];
    const float* b0_2 = (const float*)d_in[6];
    const float* W1_2 = (const float*)d_in[7];
    const float* b1_2 = (const float*)d_in[8];
    float* out = (float*)d_out;

    void* p1 = nullptr; void* p2 = nullptr;
    cudaGetSymbolAddress(&p1, g_h1);
    cudaGetSymbolAddress(&p2, g_h2);
    float* h1 = (float*)p1;
    float* h2 = (float*)p2;

    const size_t shm = (size_t)STAGES * (BM + BN) * BKP * sizeof(float);  // 110592
    cudaFuncSetAttribute(grouped_gemm<0>, cudaFuncAttributeMaxDynamicSharedMemorySize, (int)shm);
    cudaFuncSetAttribute(grouped_gemm<1>, cudaFuncAttributeMaxDynamicSharedMemorySize, (int)shm);

    dim3 blk(NTHREADS);

    // G1a: h1[b,i,k] = gelu(x1 @ W0_1[i]^T + b0_1[i])    M=256,N=2048,K=2048, G=16
    grouped_gemm<0><<<dim3(2048 / BN, 256 / BM, 16), blk, shm>>>(
        x, 2048L, 32768L, 64L,
        W0_1, 2048L * 2048L,
        b0_1,
        h1, 2048L, 32768L, 64L,
        nullptr, 2048, 2048);

    // G2a: h2[b,j,k] = gelu(x2 @ W0_2[j]^T + b0_2[j])    M=256,N=2048,K=1024, G=32
    // A gather: x2[b, i*64+d] = x[b,i,j,d] -> base x + j*64, ldr 32768, ldblk 2048
    grouped_gemm<0><<<dim3(2048 / BN, 256 / BM, 32), blk, shm>>>(
        x, 64L, 32768L, 2048L,
        W0_2, 2048L * 1024L,
        b0_2,
        h2, 2048L, 65536L, 64L,
        nullptr, 2048, 1024);

    // G1b: out[b,i,f1] = x[b,i,f1] + 0.5*(h1 @ W1_1[i]^T + b1_1[i])   N=2048,K=2048, G=16
    grouped_gemm<1><<<dim3(2048 / BN, 256 / BM, 16), blk, shm>>>(
        h1, 2048L, 32768L, 64L,
        W1_1, 2048L * 2048L,
        b1_1,
        out, 2048L, 32768L, 64L,
        x, 2048, 2048);

    // G2b: out[b,i,j,d] += 0.5*(h2 @ W1_2[j]^T + b1_2[j])   N=1024,K=2048, G=32
    // out scatter: n=(i,d) -> base out + j*64, ldr 32768, ldblk 2048; aux = out (read-modify-write)
    grouped_gemm<1><<<dim3(1024 / BN, 256 / BM, 32), blk, shm>>>(
        h2, 2048L, 65536L, 64L,
        W1_2, 1024L * 2048L,
        b1_2,
        out, 64L, 32768L, 2048L,
        out, 1024, 2048);

    (void)in_sizes; (void)n_in; (void)out_size;
}

// round 7
// speedup vs baseline: 1.0027x; 1.0007x over previous
#include <cuda_runtime.h>
#include <cstdint>

// ---------------- problem constants ----------------
// B=256, D0=16, D1=32, D2=64, D_FFN=2048, F1=2048, F2=1024
// out dtype float32, out_size = 256*16*32*64 = 8388608

#define BM 128
#define BN 128
#define BK 32
#define BKP 36          // padded smem row stride (floats) -> conflict-free frags
#define STAGES 3
#define NTHREADS 256

// scratch: h1 [B, D0, 2048] (32MB), h2 [B, D1, 2048] (64MB)
__device__ __align__(128) float g_h1[256L * 16 * 2048];
__device__ __align__(128) float g_h2[256L * 32 * 2048];

static __device__ __forceinline__ uint32_t smem_u32(const void* p) {
    return (uint32_t)__cvta_generic_to_shared(p);
}
static __device__ __forceinline__ void cp_async16(uint32_t s, const void* g) {
    asm volatile("cp.async.cg.shared.global [%0], [%1], 16;\n" :: "r"(s), "l"(g));
}
static __device__ __forceinline__ void cp_commit() {
    asm volatile("cp.async.commit_group;\n" ::: "memory");
}
template <int N_>
static __device__ __forceinline__ void cp_wait() {
    asm volatile("cp.async.wait_group %0;\n" :: "n"(N_) : "memory");
}
static __device__ __forceinline__ uint32_t f2tf32(float f) {
    uint32_t u;
    asm("cvt.rna.tf32.f32 %0, %1;\n" : "=r"(u) : "f"(f));
    return u;
}
static __device__ __forceinline__ void mma_tf32(float c[4],
                                                uint32_t a0, uint32_t a1, uint32_t a2, uint32_t a3,
                                                uint32_t b0, uint32_t b1) {
    asm volatile(
        "mma.sync.aligned.m16n8k8.row.col.f32.tf32.tf32.f32 "
        "{%0,%1,%2,%3}, {%4,%5,%6,%7}, {%8,%9}, {%0,%1,%2,%3};\n"
        : "+f"(c[0]), "+f"(c[1]), "+f"(c[2]), "+f"(c[3])
        : "r"(a0), "r"(a1), "r"(a2), "r"(a3), "r"(b0), "r"(b1));
}

// Grouped TN GEMM:  C[m,n] = sum_k A_g[m,k] * W_g[n,k]
// A addressing (handles strided gather without a transpose pass):
//   A elem (m,k)  at A0 + g*a_g + m*a_ldr + (k>>6)*a_ldblk + (k&63)
// W addressing:   W0 + g*w_g + n*K + k            (always K-contiguous)
// out addressing: out0 + g*o_g + m*o_ldr + (n>>6)*o_ldblk + (n&63)
// MODE 0: out = gelu(acc + bias[n])
// MODE 1: out = aux0[same index] + 0.5f*(acc + bias[n])
template <int MODE>
__global__ void __launch_bounds__(NTHREADS)
grouped_gemm(const float* __restrict__ A0, long a_g, long a_ldr, long a_ldblk,
             const float* __restrict__ W0, long w_g,
             const float* __restrict__ bias0,
             float* __restrict__ out0, long o_g, long o_ldr, long o_ldblk,
             const float* __restrict__ aux0,
             int N, int K) {
    extern __shared__ float smem[];
    float* As = smem;                        // [STAGES][BM][BKP]
    float* Bs = smem + (long)STAGES * BM * BKP;  // [STAGES][BN][BKP]

    const int g  = blockIdx.z;
    const int bm = blockIdx.y;
    const int bn = blockIdx.x;

    const float* A    = A0 + (long)g * a_g;
    const float* W    = W0 + (long)g * w_g;
    const float* bias = bias0 + (long)g * (long)N;

    const int tid  = threadIdx.x;
    const int lrow = tid >> 3;            // 0..31 (row within a 32-row pass)
    const int lk4  = (tid & 7) * 4;       // 0,4,...,28 (k offset of 16B chunk)

    const int warp = tid >> 5;
    const int lane = tid & 31;
    const int wm   = (warp >> 2) * 64;    // warp m offset (0 / 64)
    const int wn   = (warp & 3) * 32;     // warp n offset (0/32/64/96)
    const int qrow = lane >> 2;           // 0..7
    const int qk   = lane & 3;            // 0..3

    float c[4][4][4];
#pragma unroll
    for (int mi = 0; mi < 4; mi++)
#pragma unroll
        for (int ni = 0; ni < 4; ni++)
#pragma unroll
            for (int r = 0; r < 4; r++) c[mi][ni][r] = 0.0f;

    auto load_tile = [&](int kt, int stage) {
        float* as = As + (long)stage * BM * BKP;
        float* bs = Bs + (long)stage * BN * BKP;
        const long kg   = (long)kt * BK + lk4;
        const long ablk = (kg >> 6) * a_ldblk + (kg & 63);
#pragma unroll
        for (int p = 0; p < 4; p++) {
            const int r = lrow + p * 32;
            cp_async16(smem_u32(&as[r * BKP + lk4]),
                       A + (long)(bm * BM + r) * a_ldr + ablk);
        }
#pragma unroll
        for (int p = 0; p < 4; p++) {
            const int r = lrow + p * 32;
            cp_async16(smem_u32(&bs[r * BKP + lk4]),
                       W + (long)(bn * BN + r) * K + kg);
        }
    };

    const int KT = K / BK;

    // prologue: prefetch STAGES-1 tiles
#pragma unroll
    for (int s = 0; s < STAGES - 1; s++) {
        load_tile(s, s);
        cp_commit();
    }

    for (int kt = 0; kt < KT; kt++) {
        cp_wait<STAGES - 2>();
        __syncthreads();   // also protects the stage about to be overwritten

        const int nt = kt + STAGES - 1;
        if (nt < KT) load_tile(nt, nt % STAGES);
        cp_commit();

        const float* as = As + (long)(kt % STAGES) * BM * BKP;
        const float* bs = Bs + (long)(kt % STAGES) * BN * BKP;

#pragma unroll
        for (int ks = 0; ks < BK / 8; ks++) {
            const int k0 = ks * 8 + qk;
            uint32_t af[4][4], bf[4][2];
#pragma unroll
            for (int mi = 0; mi < 4; mi++) {
                const int m = wm + mi * 16 + qrow;
                af[mi][0] = f2tf32(as[m * BKP + k0]);
                af[mi][1] = f2tf32(as[(m + 8) * BKP + k0]);
                af[mi][2] = f2tf32(as[m * BKP + k0 + 4]);
                af[mi][3] = f2tf32(as[(m + 8) * BKP + k0 + 4]);
            }
#pragma unroll
            for (int ni = 0; ni < 4; ni++) {
                const int n = wn + ni * 8 + qrow;
                bf[ni][0] = f2tf32(bs[n * BKP + k0]);
                bf[ni][1] = f2tf32(bs[n * BKP + k0 + 4]);
            }
#pragma unroll
            for (int mi = 0; mi < 4; mi++)
#pragma unroll
                for (int ni = 0; ni < 4; ni++)
                    mma_tf32(c[mi][ni], af[mi][0], af[mi][1], af[mi][2], af[mi][3],
                             bf[ni][0], bf[ni][1]);
        }
    }
    cp_wait<0>();

    // -------- epilogue --------
    const long og = (long)g * o_g;
#pragma unroll
    for (int mi = 0; mi < 4; mi++) {
        const int mrow = bm * BM + wm + mi * 16 + qrow;
#pragma unroll
        for (int ni = 0; ni < 4; ni++) {
            const int ncol = bn * BN + wn + ni * 8 + qk * 2;
#pragma unroll
            for (int rr = 0; rr < 2; rr++) {
                const long mterm = (long)(mrow + rr * 8) * o_ldr;
#pragma unroll
                for (int cc = 0; cc < 2; cc++) {
                    const int n_g = ncol + cc;
                    const float v = c[mi][ni][rr * 2 + cc] + bias[n_g];
                    const long oaddr = og + mterm + (long)(n_g >> 6) * o_ldblk + (n_g & 63);
                    if (MODE == 0) {
                        // exact-erf GELU
                        out0[oaddr] = 0.5f * v * (1.0f + erff(v * 0.70710678118654752f));
                    } else {
                        out0[oaddr] = aux0[oaddr] + 0.5f * v;
                    }
                }
            }
        }
    }
}

extern "C" void kernel_launch(void* const* d_in, const int* in_sizes, int n_in,
                              void* d_out, int out_size) {
    const float* x    = (const float*)d_in[0];
    const float* W0_1 = (const float*)d_in[1];
    const float* b0_1 = (const float*)d_in[2];
    const float* W1_1 = (const float*)d_in[3];
    const float* b1_1 = (const float*)d_in[4];
    const float* W0_2 = (const float*)d_in[5];
    const float* b0_2 = (const float*)d_in[6];
    const float* W1_2 = (const float*)d_in[7];
    const float* b1_2 = (const float*)d_in[8];
    float* out = (float*)d_out;

    void* p1 = nullptr; void* p2 = nullptr;
    cudaGetSymbolAddress(&p1, g_h1);
    cudaGetSymbolAddress(&p2, g_h2);
    float* h1 = (float*)p1;
    float* h2 = (float*)p2;

    const size_t shm = (size_t)STAGES * (BM + BN) * BKP * sizeof(float);  // 110592
    cudaFuncSetAttribute(grouped_gemm<0>, cudaFuncAttributeMaxDynamicSharedMemorySize, (int)shm);
    cudaFuncSetAttribute(grouped_gemm<1>, cudaFuncAttributeMaxDynamicSharedMemorySize, (int)shm);

    dim3 blk(NTHREADS);

    // G1a: h1[b,i,k] = gelu(x1 @ W0_1[i]^T + b0_1[i])    M=256,N=2048,K=2048, G=16
    grouped_gemm<0><<<dim3(2048 / BN, 256 / BM, 16), blk, shm>>>(
        x, 2048L, 32768L, 64L,
        W0_1, 2048L * 2048L,
        b0_1,
        h1, 2048L, 32768L, 64L,
        nullptr, 2048, 2048);

    // G2a: h2[b,j,k] = gelu(x2 @ W0_2[j]^T + b0_2[j])    M=256,N=2048,K=1024, G=32
    // A gather: x2[b, i*64+d] = x[b,i,j,d] -> base x + j*64, ldr 32768, ldblk 2048
    grouped_gemm<0><<<dim3(2048 / BN, 256 / BM, 32), blk, shm>>>(
        x, 64L, 32768L, 2048L,
        W0_2, 2048L * 1024L,
        b0_2,
        h2, 2048L, 65536L, 64L,
        nullptr, 2048, 1024);

    // G1b: out[b,i,f1] = x[b,i,f1] + 0.5*(h1 @ W1_1[i]^T + b1_1[i])   N=2048,K=2048, G=16
    grouped_gemm<1><<<dim3(2048 / BN, 256 / BM, 16), blk, shm>>>(
        h1, 2048L, 32768L, 64L,
        W1_1, 2048L * 2048L,
        b1_1,
        out, 2048L, 32768L, 64L,
        x, 2048, 2048);

    // G2b: out[b,i,j,d] += 0.5*(h2 @ W1_2[j]^T + b1_2[j])   N=1024,K=2048, G=32
    // out scatter: n=(i,d) -> base out + j*64, ldr 32768, ldblk 2048; aux = out (read-modify-write)
    grouped_gemm<1><<<dim3(1024 / BN, 256 / BM, 32), blk, shm>>>(
        h2, 2048L, 65536L, 64L,
        W1_2, 1024L * 2048L,
        b1_2,
        out, 64L, 32768L, 2048L,
        out, 1024, 2048);

    (void)in_sizes; (void)n_in; (void)out_size;
}

// round 8
// speedup vs baseline: 1.0029x; 1.0002x over previous
#include <cuda_runtime.h>
#include <cstdint>

// ---------------- problem constants ----------------
// B=256, D0=16, D1=32, D2=64, D_FFN=2048, F1=2048, F2=1024
// out dtype float32, out_size = 256*16*32*64 = 8388608

#define BM 128
#define BN 128
#define BK 32
#define BKP 36          // padded smem row stride (floats) -> conflict-free frags
#define STAGES 3
#define NTHREADS 256

// scratch: h1 [B, D0, 2048] (32MB), h2 [B, D1, 2048] (64MB)
__device__ __align__(128) float g_h1[256L * 16 * 2048];
__device__ __align__(128) float g_h2[256L * 32 * 2048];

static __device__ __forceinline__ uint32_t smem_u32(const void* p) {
    return (uint32_t)__cvta_generic_to_shared(p);
}
static __device__ __forceinline__ void cp_async16(uint32_t s, const void* g) {
    asm volatile("cp.async.cg.shared.global [%0], [%1], 16;\n" :: "r"(s), "l"(g));
}
static __device__ __forceinline__ void cp_commit() {
    asm volatile("cp.async.commit_group;\n" ::: "memory");
}
template <int N_>
static __device__ __forceinline__ void cp_wait() {
    asm volatile("cp.async.wait_group %0;\n" :: "n"(N_) : "memory");
}
static __device__ __forceinline__ uint32_t f2tf32(float f) {
    uint32_t u;
    asm("cvt.rna.tf32.f32 %0, %1;\n" : "=r"(u) : "f"(f));
    return u;
}
static __device__ __forceinline__ void mma_tf32(float c[4],
                                                uint32_t a0, uint32_t a1, uint32_t a2, uint32_t a3,
                                                uint32_t b0, uint32_t b1) {
    asm volatile(
        "mma.sync.aligned.m16n8k8.row.col.f32.tf32.tf32.f32 "
        "{%0,%1,%2,%3}, {%4,%5,%6,%7}, {%8,%9}, {%0,%1,%2,%3};\n"
        : "+f"(c[0]), "+f"(c[1]), "+f"(c[2]), "+f"(c[3])
        : "r"(a0), "r"(a1), "r"(a2), "r"(a3), "r"(b0), "r"(b1));
}

// Grouped TN GEMM:  C[m,n] = sum_k A_g[m,k] * W_g[n,k]
// A addressing (handles strided gather without a transpose pass):
//   A elem (m,k)  at A0 + g*a_g + m*a_ldr + (k>>6)*a_ldblk + (k&63)
// W addressing:   W0 + g*w_g + n*K + k            (always K-contiguous)
// out addressing: out0 + g*o_g + m*o_ldr + (n>>6)*o_ldblk + (n&63)
// MODE 0: out = gelu(acc + bias[n])
// MODE 1: out = aux0[same index] + 0.5f*(acc + bias[n])
template <int MODE>
__global__ void __launch_bounds__(NTHREADS)
grouped_gemm(const float* __restrict__ A0, long a_g, long a_ldr, long a_ldblk,
             const float* __restrict__ W0, long w_g,
             const float* __restrict__ bias0,
             float* __restrict__ out0, long o_g, long o_ldr, long o_ldblk,
             const float* __restrict__ aux0,
             int N, int K) {
    extern __shared__ float smem[];
    float* As = smem;                        // [STAGES][BM][BKP]
    float* Bs = smem + (long)STAGES * BM * BKP;  // [STAGES][BN][BKP]

    const int g  = blockIdx.z;
    const int bm = blockIdx.y;
    const int bn = blockIdx.x;

    const float* A    = A0 + (long)g * a_g;
    const float* W    = W0 + (long)g * w_g;
    const float* bias = bias0 + (long)g * (long)N;

    const int tid  = threadIdx.x;
    const int lrow = tid >> 3;            // 0..31 (row within a 32-row pass)
    const int lk4  = (tid & 7) * 4;       // 0,4,...,28 (k offset of 16B chunk)

    const int warp = tid >> 5;
    const int lane = tid & 31;
    const int wm   = (warp >> 2) * 64;    // warp m offset (0 / 64)
    const int wn   = (warp & 3) * 32;     // warp n offset (0/32/64/96)
    const int qrow = lane >> 2;           // 0..7
    const int qk   = lane & 3;            // 0..3

    float c[4][4][4];
#pragma unroll
    for (int mi = 0; mi < 4; mi++)
#pragma unroll
        for (int ni = 0; ni < 4; ni++)
#pragma unroll
            for (int r = 0; r < 4; r++) c[mi][ni][r] = 0.0f;

    auto load_tile = [&](int kt, int stage) {
        float* as = As + (long)stage * BM * BKP;
        float* bs = Bs + (long)stage * BN * BKP;
        const long kg   = (long)kt * BK + lk4;
        const long ablk = (kg >> 6) * a_ldblk + (kg & 63);
#pragma unroll
        for (int p = 0; p < 4; p++) {
            const int r = lrow + p * 32;
            cp_async16(smem_u32(&as[r * BKP + lk4]),
                       A + (long)(bm * BM + r) * a_ldr + ablk);
        }
#pragma unroll
        for (int p = 0; p < 4; p++) {
            const int r = lrow + p * 32;
            cp_async16(smem_u32(&bs[r * BKP + lk4]),
                       W + (long)(bn * BN + r) * K + kg);
        }
    };

    const int KT = K / BK;

    // prologue: prefetch STAGES-1 tiles
#pragma unroll
    for (int s = 0; s < STAGES - 1; s++) {
        load_tile(s, s);
        cp_commit();
    }

    for (int kt = 0; kt < KT; kt++) {
        cp_wait<STAGES - 2>();
        __syncthreads();   // also protects the stage about to be overwritten

        const int nt = kt + STAGES - 1;
        if (nt < KT) load_tile(nt, nt % STAGES);
        cp_commit();

        const float* as = As + (long)(kt % STAGES) * BM * BKP;
        const float* bs = Bs + (long)(kt % STAGES) * BN * BKP;

#pragma unroll
        for (int ks = 0; ks < BK / 8; ks++) {
            const int k0 = ks * 8 + qk;
            uint32_t af[4][4], bf[4][2];
#pragma unroll
            for (int mi = 0; mi < 4; mi++) {
                const int m = wm + mi * 16 + qrow;
                af[mi][0] = f2tf32(as[m * BKP + k0]);
                af[mi][1] = f2tf32(as[(m + 8) * BKP + k0]);
                af[mi][2] = f2tf32(as[m * BKP + k0 + 4]);
                af[mi][3] = f2tf32(as[(m + 8) * BKP + k0 + 4]);
            }
#pragma unroll
            for (int ni = 0; ni < 4; ni++) {
                const int n = wn + ni * 8 + qrow;
                bf[ni][0] = f2tf32(bs[n * BKP + k0]);
                bf[ni][1] = f2tf32(bs[n * BKP + k0 + 4]);
            }
#pragma unroll
            for (int mi = 0; mi < 4; mi++)
#pragma unroll
                for (int ni = 0; ni < 4; ni++)
                    mma_tf32(c[mi][ni], af[mi][0], af[mi][1], af[mi][2], af[mi][3],
                             bf[ni][0], bf[ni][1]);
        }
    }
    cp_wait<0>();

    // -------- epilogue --------
    const long og = (long)g * o_g;
#pragma unroll
    for (int mi = 0; mi < 4; mi++) {
        const int mrow = bm * BM + wm + mi * 16 + qrow;
#pragma unroll
        for (int ni = 0; ni < 4; ni++) {
            const int ncol = bn * BN + wn + ni * 8 + qk * 2;
#pragma unroll
            for (int rr = 0; rr < 2; rr++) {
                const long mterm = (long)(mrow + rr * 8) * o_ldr;
#pragma unroll
                for (int cc = 0; cc < 2; cc++) {
                    const int n_g = ncol + cc;
                    const float v = c[mi][ni][rr * 2 + cc] + bias[n_g];
                    const long oaddr = og + mterm + (long)(n_g >> 6) * o_ldblk + (n_g & 63);
                    if (MODE == 0) {
                        // exact-erf GELU
                        out0[oaddr] = 0.5f * v * (1.0f + erff(v * 0.70710678118654752f));
                    } else {
                        out0[oaddr] = aux0[oaddr] + 0.5f * v;
                    }
                }
            }
        }
    }
}

extern "C" void kernel_launch(void* const* d_in, const int* in_sizes, int n_in,
                              void* d_out, int out_size) {
    const float* x    = (const float*)d_in[0];
    const float* W0_1 = (const float*)d_in[1];
    const float* b0_1 = (const float*)d_in[2];
    const float* W1_1 = (const float*)d_in[3];
    const float* b1_1 = (const float*)d_in[4];
    const float* W0_2 = (const float*)d_in[5];
    const float* b0_2 = (const float*)d_in[6];
    const float* W1_2 = (const float*)d_in[7];
    const float* b1_2 = (const float*)d_in[8];
    float* out = (float*)d_out;

    void* p1 = nullptr; void* p2 = nullptr;
    cudaGetSymbolAddress(&p1, g_h1);
    cudaGetSymbolAddress(&p2, g_h2);
    float* h1 = (float*)p1;
    float* h2 = (float*)p2;

    const size_t shm = (size_t)STAGES * (BM + BN) * BKP * sizeof(float);  // 110592
    cudaFuncSetAttribute(grouped_gemm<0>, cudaFuncAttributeMaxDynamicSharedMemorySize, (int)shm);
    cudaFuncSetAttribute(grouped_gemm<1>, cudaFuncAttributeMaxDynamicSharedMemorySize, (int)shm);

    dim3 blk(NTHREADS);

    // G1a: h1[b,i,k] = gelu(x1 @ W0_1[i]^T + b0_1[i])    M=256,N=2048,K=2048, G=16
    grouped_gemm<0><<<dim3(2048 / BN, 256 / BM, 16), blk, shm>>>(
        x, 2048L, 32768L, 64L,
        W0_1, 2048L * 2048L,
        b0_1,
        h1, 2048L, 32768L, 64L,
        nullptr, 2048, 2048);

    // G2a: h2[b,j,k] = gelu(x2 @ W0_2[j]^T + b0_2[j])    M=256,N=2048,K=1024, G=32
    // A gather: x2[b, i*64+d] = x[b,i,j,d] -> base x + j*64, ldr 32768, ldblk 2048
    grouped_gemm<0><<<dim3(2048 / BN, 256 / BM, 32), blk, shm>>>(
        x, 64L, 32768L, 2048L,
        W0_2, 2048L * 1024L,
        b0_2,
        h2, 2048L, 65536L, 64L,
        nullptr, 2048, 1024);

    // G1b: out[b,i,f1] = x[b,i,f1] + 0.5*(h1 @ W1_1[i]^T + b1_1[i])   N=2048,K=2048, G=16
    grouped_gemm<1><<<dim3(2048 / BN, 256 / BM, 16), blk, shm>>>(
        h1, 2048L, 32768L, 64L,
        W1_1, 2048L * 2048L,
        b1_1,
        out, 2048L, 32768L, 64L,
        x, 2048, 2048);

    // G2b: out[b,i,j,d] += 0.5*(h2 @ W1_2[j]^T + b1_2[j])   N=1024,K=2048, G=32
    // out scatter: n=(i,d) -> base out + j*64, ldr 32768, ldblk 2048; aux = out (read-modify-write)
    grouped_gemm<1><<<dim3(1024 / BN, 256 / BM, 32), blk, shm>>>(
        h2, 2048L, 65536L, 64L,
        W1_2, 1024L * 2048L,
        b1_2,
        out, 64L, 32768L, 2048L,
        out, 1024, 2048);

    (void)in_sizes; (void)n_in; (void)out_size;
}

// round 9
// speedup vs baseline: 1.0050x; 1.0021x over previous
#include <cuda_runtime.h>
#include <cstdint>

// ---------------- problem constants ----------------
// B=256, D0=16, D1=32, D2=64, D_FFN=2048, F1=2048, F2=1024
// out dtype float32, out_size = 256*16*32*64 = 8388608

#define BM 128
#define BN 128
#define BK 32
#define BKP 36          // padded smem row stride (floats) -> conflict-free frags
#define STAGES 3
#define NTHREADS 256

// scratch: h1 [B, D0, 2048] (32MB), h2 [B, D1, 2048] (64MB)
__device__ __align__(128) float g_h1[256L * 16 * 2048];
__device__ __align__(128) float g_h2[256L * 32 * 2048];

static __device__ __forceinline__ uint32_t smem_u32(const void* p) {
    return (uint32_t)__cvta_generic_to_shared(p);
}
static __device__ __forceinline__ void cp_async16(uint32_t s, const void* g) {
    asm volatile("cp.async.cg.shared.global [%0], [%1], 16;\n" :: "r"(s), "l"(g));
}
static __device__ __forceinline__ void cp_commit() {
    asm volatile("cp.async.commit_group;\n" ::: "memory");
}
template <int N_>
static __device__ __forceinline__ void cp_wait() {
    asm volatile("cp.async.wait_group %0;\n" :: "n"(N_) : "memory");
}
static __device__ __forceinline__ uint32_t f2tf32(float f) {
    uint32_t u;
    asm("cvt.rna.tf32.f32 %0, %1;\n" : "=r"(u) : "f"(f));
    return u;
}
static __device__ __forceinline__ void mma_tf32(float c[4],
                                                uint32_t a0, uint32_t a1, uint32_t a2, uint32_t a3,
                                                uint32_t b0, uint32_t b1) {
    asm volatile(
        "mma.sync.aligned.m16n8k8.row.col.f32.tf32.tf32.f32 "
        "{%0,%1,%2,%3}, {%4,%5,%6,%7}, {%8,%9}, {%0,%1,%2,%3};\n"
        : "+f"(c[0]), "+f"(c[1]), "+f"(c[2]), "+f"(c[3])
        : "r"(a0), "r"(a1), "r"(a2), "r"(a3), "r"(b0), "r"(b1));
}

// Grouped TN GEMM:  C[m,n] = sum_k A_g[m,k] * W_g[n,k]
// A addressing (handles strided gather without a transpose pass):
//   A elem (m,k)  at A0 + g*a_g + m*a_ldr + (k>>6)*a_ldblk + (k&63)
// W addressing:   W0 + g*w_g + n*K + k            (always K-contiguous)
// out addressing: out0 + g*o_g + m*o_ldr + (n>>6)*o_ldblk + (n&63)
// MODE 0: out = gelu(acc + bias[n])
// MODE 1: out = aux0[same index] + 0.5f*(acc + bias[n])
template <int MODE>
__global__ void __launch_bounds__(NTHREADS)
grouped_gemm(const float* __restrict__ A0, long a_g, long a_ldr, long a_ldblk,
             const float* __restrict__ W0, long w_g,
             const float* __restrict__ bias0,
             float* __restrict__ out0, long o_g, long o_ldr, long o_ldblk,
             const float* __restrict__ aux0,
             int N, int K) {
    extern __shared__ float smem[];
    float* As = smem;                        // [STAGES][BM][BKP]
    float* Bs = smem + (long)STAGES * BM * BKP;  // [STAGES][BN][BKP]

    const int g  = blockIdx.z;
    const int bm = blockIdx.y;
    const int bn = blockIdx.x;

    const float* A    = A0 + (long)g * a_g;
    const float* W    = W0 + (long)g * w_g;
    const float* bias = bias0 + (long)g * (long)N;

    const int tid  = threadIdx.x;
    const int lrow = tid >> 3;            // 0..31 (row within a 32-row pass)
    const int lk4  = (tid & 7) * 4;       // 0,4,...,28 (k offset of 16B chunk)

    const int warp = tid >> 5;
    const int lane = tid & 31;
    const int wm   = (warp >> 2) * 64;    // warp m offset (0 / 64)
    const int wn   = (warp & 3) * 32;     // warp n offset (0/32/64/96)
    const int qrow = lane >> 2;           // 0..7
    const int qk   = lane & 3;            // 0..3

    float c[4][4][4];
#pragma unroll
    for (int mi = 0; mi < 4; mi++)
#pragma unroll
        for (int ni = 0; ni < 4; ni++)
#pragma unroll
            for (int r = 0; r < 4; r++) c[mi][ni][r] = 0.0f;

    auto load_tile = [&](int kt, int stage) {
        float* as = As + (long)stage * BM * BKP;
        float* bs = Bs + (long)stage * BN * BKP;
        const long kg   = (long)kt * BK + lk4;
        const long ablk = (kg >> 6) * a_ldblk + (kg & 63);
#pragma unroll
        for (int p = 0; p < 4; p++) {
            const int r = lrow + p * 32;
            cp_async16(smem_u32(&as[r * BKP + lk4]),
                       A + (long)(bm * BM + r) * a_ldr + ablk);
        }
#pragma unroll
        for (int p = 0; p < 4; p++) {
            const int r = lrow + p * 32;
            cp_async16(smem_u32(&bs[r * BKP + lk4]),
                       W + (long)(bn * BN + r) * K + kg);
        }
    };

    const int KT = K / BK;

    // prologue: prefetch STAGES-1 tiles
#pragma unroll
    for (int s = 0; s < STAGES - 1; s++) {
        load_tile(s, s);
        cp_commit();
    }

    for (int kt = 0; kt < KT; kt++) {
        cp_wait<STAGES - 2>();
        __syncthreads();   // also protects the stage about to be overwritten

        const int nt = kt + STAGES - 1;
        if (nt < KT) load_tile(nt, nt % STAGES);
        cp_commit();

        const float* as = As + (long)(kt % STAGES) * BM * BKP;
        const float* bs = Bs + (long)(kt % STAGES) * BN * BKP;

#pragma unroll
        for (int ks = 0; ks < BK / 8; ks++) {
            const int k0 = ks * 8 + qk;
            uint32_t af[4][4], bf[4][2];
#pragma unroll
            for (int mi = 0; mi < 4; mi++) {
                const int m = wm + mi * 16 + qrow;
                af[mi][0] = f2tf32(as[m * BKP + k0]);
                af[mi][1] = f2tf32(as[(m + 8) * BKP + k0]);
                af[mi][2] = f2tf32(as[m * BKP + k0 + 4]);
                af[mi][3] = f2tf32(as[(m + 8) * BKP + k0 + 4]);
            }
#pragma unroll
            for (int ni = 0; ni < 4; ni++) {
                const int n = wn + ni * 8 + qrow;
                bf[ni][0] = f2tf32(bs[n * BKP + k0]);
                bf[ni][1] = f2tf32(bs[n * BKP + k0 + 4]);
            }
#pragma unroll
            for (int mi = 0; mi < 4; mi++)
#pragma unroll
                for (int ni = 0; ni < 4; ni++)
                    mma_tf32(c[mi][ni], af[mi][0], af[mi][1], af[mi][2], af[mi][3],
                             bf[ni][0], bf[ni][1]);
        }
    }
    cp_wait<0>();

    // -------- epilogue --------
    const long og = (long)g * o_g;
#pragma unroll
    for (int mi = 0; mi < 4; mi++) {
        const int mrow = bm * BM + wm + mi * 16 + qrow;
#pragma unroll
        for (int ni = 0; ni < 4; ni++) {
            const int ncol = bn * BN + wn + ni * 8 + qk * 2;
#pragma unroll
            for (int rr = 0; rr < 2; rr++) {
                const long mterm = (long)(mrow + rr * 8) * o_ldr;
#pragma unroll
                for (int cc = 0; cc < 2; cc++) {
                    const int n_g = ncol + cc;
                    const float v = c[mi][ni][rr * 2 + cc] + bias[n_g];
                    const long oaddr = og + mterm + (long)(n_g >> 6) * o_ldblk + (n_g & 63);
                    if (MODE == 0) {
                        // exact-erf GELU
                        out0[oaddr] = 0.5f * v * (1.0f + erff(v * 0.70710678118654752f));
                    } else {
                        out0[oaddr] = aux0[oaddr] + 0.5f * v;
                    }
                }
            }
        }
    }
}

extern "C" void kernel_launch(void* const* d_in, const int* in_sizes, int n_in,
                              void* d_out, int out_size) {
    const float* x    = (const float*)d_in[0];
    const float* W0_1 = (const float*)d_in[1];
    const float* b0_1 = (const float*)d_in[2];
    const float* W1_1 = (const float*)d_in[3];
    const float* b1_1 = (const float*)d_in[4];
    const float* W0_2 = (const float*)d_in[5];
    const float* b0_2 = (const float*)d_in[6];
    const float* W1_2 = (const float*)d_in[7];
    const float* b1_2 = (const float*)d_in[8];
    float* out = (float*)d_out;

    void* p1 = nullptr; void* p2 = nullptr;
    cudaGetSymbolAddress(&p1, g_h1);
    cudaGetSymbolAddress(&p2, g_h2);
    float* h1 = (float*)p1;
    float* h2 = (float*)p2;

    const size_t shm = (size_t)STAGES * (BM + BN) * BKP * sizeof(float);  // 110592
    cudaFuncSetAttribute(grouped_gemm<0>, cudaFuncAttributeMaxDynamicSharedMemorySize, (int)shm);
    cudaFuncSetAttribute(grouped_gemm<1>, cudaFuncAttributeMaxDynamicSharedMemorySize, (int)shm);

    dim3 blk(NTHREADS);

    // G1a: h1[b,i,k] = gelu(x1 @ W0_1[i]^T + b0_1[i])    M=256,N=2048,K=2048, G=16
    grouped_gemm<0><<<dim3(2048 / BN, 256 / BM, 16), blk, shm>>>(
        x, 2048L, 32768L, 64L,
        W0_1, 2048L * 2048L,
        b0_1,
        h1, 2048L, 32768L, 64L,
        nullptr, 2048, 2048);

    // G2a: h2[b,j,k] = gelu(x2 @ W0_2[j]^T + b0_2[j])    M=256,N=2048,K=1024, G=32
    // A gather: x2[b, i*64+d] = x[b,i,j,d] -> base x + j*64, ldr 32768, ldblk 2048
    grouped_gemm<0><<<dim3(2048 / BN, 256 / BM, 32), blk, shm>>>(
        x, 64L, 32768L, 2048L,
        W0_2, 2048L * 1024L,
        b0_2,
        h2, 2048L, 65536L, 64L,
        nullptr, 2048, 1024);

    // G1b: out[b,i,f1] = x[b,i,f1] + 0.5*(h1 @ W1_1[i]^T + b1_1[i])   N=2048,K=2048, G=16
    grouped_gemm<1><<<dim3(2048 / BN, 256 / BM, 16), blk, shm>>>(
        h1, 2048L, 32768L, 64L,
        W1_1, 2048L * 2048L,
        b1_1,
        out, 2048L, 32768L, 64L,
        x, 2048, 2048);

    // G2b: out[b,i,j,d] += 0.5*(h2 @ W1_2[j]^T + b1_2[j])   N=1024,K=2048, G=32
    // out scatter: n=(i,d) -> base out + j*64, ldr 32768, ldblk 2048; aux = out (read-modify-write)
    grouped_gemm<1><<<dim3(1024 / BN, 256 / BM, 32), blk, shm>>>(
        h2, 2048L, 65536L, 64L,
        W1_2, 1024L * 2048L,
        b1_2,
        out, 64L, 32768L, 2048L,
        out, 1024, 2048);

    (void)in_sizes; (void)n_in; (void)out_size;
}

// round 10
// speedup vs baseline: 1.3056x; 1.2991x over previous
#include <cuda_runtime.h>
#include <cstdint>

// ---------------- problem constants ----------------
// B=256, D0=16, D1=32, D2=64, D_FFN=2048, F1=2048, F2=1024
// out dtype float32, out_size = 256*16*32*64 = 8388608

#define BM 128
#define BN 128
#define BK 32
#define BKP 36          // padded smem row stride (floats) -> conflict-free frags
#define STAGES 3
#define NTHREADS 256

// scratch: h1 [B, D0, 2048] (32MB), h2 [B, D1, 2048] (64MB)
__device__ __align__(128) float g_h1[256L * 16 * 2048];
__device__ __align__(128) float g_h2[256L * 32 * 2048];

static __device__ __forceinline__ uint32_t smem_u32(const void* p) {
    return (uint32_t)__cvta_generic_to_shared(p);
}
static __device__ __forceinline__ void cp_async16(uint32_t s, const void* g) {
    asm volatile("cp.async.cg.shared.global [%0], [%1], 16;\n" :: "r"(s), "l"(g));
}
static __device__ __forceinline__ void cp_commit() {
    asm volatile("cp.async.commit_group;\n" ::: "memory");
}
template <int N_>
static __device__ __forceinline__ void cp_wait() {
    asm volatile("cp.async.wait_group %0;\n" :: "n"(N_) : "memory");
}
// NOTE: no cvt.rna.tf32 — HMMA.tf32 reads bits[31:13] of the operand register,
// so raw fp32 bits act as round-toward-zero tf32 (CUTLASS fast path).
static __device__ __forceinline__ void mma_tf32(float c[4],
                                                uint32_t a0, uint32_t a1, uint32_t a2, uint32_t a3,
                                                uint32_t b0, uint32_t b1) {
    asm volatile(
        "mma.sync.aligned.m16n8k8.row.col.f32.tf32.tf32.f32 "
        "{%0,%1,%2,%3}, {%4,%5,%6,%7}, {%8,%9}, {%0,%1,%2,%3};\n"
        : "+f"(c[0]), "+f"(c[1]), "+f"(c[2]), "+f"(c[3])
        : "r"(a0), "r"(a1), "r"(a2), "r"(a3), "r"(b0), "r"(b1));
}

// Grouped TN GEMM:  C[m,n] = sum_k A_g[m,k] * W_g[n,k]
// A addressing (handles strided gather without a transpose pass):
//   A elem (m,k)  at A0 + g*a_g + m*a_ldr + (k>>6)*a_ldblk + (k&63)
// W addressing:   W0 + g*w_g + n*K + k            (always K-contiguous)
// out addressing: out0 + g*o_g + m*o_ldr + (n>>6)*o_ldblk + (n&63)
// MODE 0: out = gelu(acc + bias[n])
// MODE 1: out = aux0[same index] + 0.5f*(acc + bias[n])
template <int MODE>
__global__ void __launch_bounds__(NTHREADS, 2)
grouped_gemm(const float* __restrict__ A0, long a_g, long a_ldr, long a_ldblk,
             const float* __restrict__ W0, long w_g,
             const float* __restrict__ bias0,
             float* __restrict__ out0, long o_g, long o_ldr, long o_ldblk,
             const float* __restrict__ aux0,
             int N, int K) {
    extern __shared__ float smem[];
    float* As = smem;                        // [STAGES][BM][BKP]
    float* Bs = smem + (long)STAGES * BM * BKP;  // [STAGES][BN][BKP]

    const int g  = blockIdx.z;
    const int bm = blockIdx.y;
    const int bn = blockIdx.x;

    const float* A    = A0 + (long)g * a_g;
    const float* W    = W0 + (long)g * w_g;
    const float* bias = bias0 + (long)g * (long)N;

    const int tid  = threadIdx.x;
    const int lrow = tid >> 3;            // 0..31 (row within a 32-row pass)
    const int lk4  = (tid & 7) * 4;       // 0,4,...,28 (k offset of 16B chunk)

    const int warp = tid >> 5;
    const int lane = tid & 31;
    const int wm   = (warp >> 2) * 64;    // warp m offset (0 / 64)
    const int wn   = (warp & 3) * 32;     // warp n offset (0/32/64/96)
    const int qrow = lane >> 2;           // 0..7
    const int qk   = lane & 3;            // 0..3

    float c[4][4][4];
#pragma unroll
    for (int mi = 0; mi < 4; mi++)
#pragma unroll
        for (int ni = 0; ni < 4; ni++)
#pragma unroll
            for (int r = 0; r < 4; r++) c[mi][ni][r] = 0.0f;

    auto load_tile = [&](int kt, int stage) {
        float* as = As + (long)stage * BM * BKP;
        float* bs = Bs + (long)stage * BN * BKP;
        const long kg   = (long)kt * BK + lk4;
        const long ablk = (kg >> 6) * a_ldblk + (kg & 63);
#pragma unroll
        for (int p = 0; p < 4; p++) {
            const int r = lrow + p * 32;
            cp_async16(smem_u32(&as[r * BKP + lk4]),
                       A + (long)(bm * BM + r) * a_ldr + ablk);
        }
#pragma unroll
        for (int p = 0; p < 4; p++) {
            const int r = lrow + p * 32;
            cp_async16(smem_u32(&bs[r * BKP + lk4]),
                       W + (long)(bn * BN + r) * K + kg);
        }
    };

    const int KT = K / BK;

    // prologue: prefetch STAGES-1 tiles
#pragma unroll
    for (int s = 0; s < STAGES - 1; s++) {
        load_tile(s, s);
        cp_commit();
    }

    for (int kt = 0; kt < KT; kt++) {
        cp_wait<STAGES - 2>();
        __syncthreads();   // also protects the stage about to be overwritten

        const int nt = kt + STAGES - 1;
        if (nt < KT) load_tile(nt, nt % STAGES);
        cp_commit();

        // read fragments as raw bits (no cvt; tf32 HMMA ignores low 13 bits)
        const uint32_t* as = (const uint32_t*)(As + (long)(kt % STAGES) * BM * BKP);
        const uint32_t* bs = (const uint32_t*)(Bs + (long)(kt % STAGES) * BN * BKP);

#pragma unroll
        for (int ks = 0; ks < BK / 8; ks++) {
            const int k0 = ks * 8 + qk;
            uint32_t af[4][4], bf[4][2];
#pragma unroll
            for (int mi = 0; mi < 4; mi++) {
                const int m = wm + mi * 16 + qrow;
                af[mi][0] = as[m * BKP + k0];
                af[mi][1] = as[(m + 8) * BKP + k0];
                af[mi][2] = as[m * BKP + k0 + 4];
                af[mi][3] = as[(m + 8) * BKP + k0 + 4];
            }
#pragma unroll
            for (int ni = 0; ni < 4; ni++) {
                const int n = wn + ni * 8 + qrow;
                bf[ni][0] = bs[n * BKP + k0];
                bf[ni][1] = bs[n * BKP + k0 + 4];
            }
#pragma unroll
            for (int mi = 0; mi < 4; mi++)
#pragma unroll
                for (int ni = 0; ni < 4; ni++)
                    mma_tf32(c[mi][ni], af[mi][0], af[mi][1], af[mi][2], af[mi][3],
                             bf[ni][0], bf[ni][1]);
        }
    }
    cp_wait<0>();

    // -------- epilogue --------
    const long og = (long)g * o_g;
#pragma unroll
    for (int mi = 0; mi < 4; mi++) {
        const int mrow = bm * BM + wm + mi * 16 + qrow;
#pragma unroll
        for (int ni = 0; ni < 4; ni++) {
            const int ncol = bn * BN + wn + ni * 8 + qk * 2;
#pragma unroll
            for (int rr = 0; rr < 2; rr++) {
                const long mterm = (long)(mrow + rr * 8) * o_ldr;
#pragma unroll
                for (int cc = 0; cc < 2; cc++) {
                    const int n_g = ncol + cc;
                    const float v = c[mi][ni][rr * 2 + cc] + bias[n_g];
                    const long oaddr = og + mterm + (long)(n_g >> 6) * o_ldblk + (n_g & 63);
                    if (MODE == 0) {
                        // exact-erf GELU
                        out0[oaddr] = 0.5f * v * (1.0f + erff(v * 0.70710678118654752f));
                    } else {
                        out0[oaddr] = aux0[oaddr] + 0.5f * v;
                    }
                }
            }
        }
    }
}

extern "C" void kernel_launch(void* const* d_in, const int* in_sizes, int n_in,
                              void* d_out, int out_size) {
    const float* x    = (const float*)d_in[0];
    const float* W0_1 = (const float*)d_in[1];
    const float* b0_1 = (const float*)d_in[2];
    const float* W1_1 = (const float*)d_in[3];
    const float* b1_1 = (const float*)d_in[4];
    const float* W0_2 = (const float*)d_in[5];
    const float* b0_2 = (const float*)d_in[6];
    const float* W1_2 = (const float*)d_in[7];
    const float* b1_2 = (const float*)d_in[8];
    float* out = (float*)d_out;

    void* p1 = nullptr; void* p2 = nullptr;
    cudaGetSymbolAddress(&p1, g_h1);
    cudaGetSymbolAddress(&p2, g_h2);
    float* h1 = (float*)p1;
    float* h2 = (float*)p2;

    const size_t shm = (size_t)STAGES * (BM + BN) * BKP * sizeof(float);  // 110592
    cudaFuncSetAttribute(grouped_gemm<0>, cudaFuncAttributeMaxDynamicSharedMemorySize, (int)shm);
    cudaFuncSetAttribute(grouped_gemm<1>, cudaFuncAttributeMaxDynamicSharedMemorySize, (int)shm);

    dim3 blk(NTHREADS);

    // G1a: h1[b,i,k] = gelu(x1 @ W0_1[i]^T + b0_1[i])    M=256,N=2048,K=2048, G=16
    grouped_gemm<0><<<dim3(2048 / BN, 256 / BM, 16), blk, shm>>>(
        x, 2048L, 32768L, 64L,
        W0_1, 2048L * 2048L,
        b0_1,
        h1, 2048L, 32768L, 64L,
        nullptr, 2048, 2048);

    // G2a: h2[b,j,k] = gelu(x2 @ W0_2[j]^T + b0_2[j])    M=256,N=2048,K=1024, G=32
    // A gather: x2[b, i*64+d] = x[b,i,j,d] -> base x + j*64, ldr 32768, ldblk 2048
    grouped_gemm<0><<<dim3(2048 / BN, 256 / BM, 32), blk, shm>>>(
        x, 64L, 32768L, 2048L,
        W0_2, 2048L * 1024L,
        b0_2,
        h2, 2048L, 65536L, 64L,
        nullptr, 2048, 1024);

    // G1b: out[b,i,f1] = x[b,i,f1] + 0.5*(h1 @ W1_1[i]^T + b1_1[i])   N=2048,K=2048, G=16
    grouped_gemm<1><<<dim3(2048 / BN, 256 / BM, 16), blk, shm>>>(
        h1, 2048L, 32768L, 64L,
        W1_1, 2048L * 2048L,
        b1_1,
        out, 2048L, 32768L, 64L,
        x, 2048, 2048);

    // G2b: out[b,i,j,d] += 0.5*(h2 @ W1_2[j]^T + b1_2[j])   N=1024,K=2048, G=32
    // out scatter: n=(i,d) -> base out + j*64, ldr 32768, ldblk 2048; aux = out (read-modify-write)
    grouped_gemm<1><<<dim3(1024 / BN, 256 / BM, 32), blk, shm>>>(
        h2, 2048L, 65536L, 64L,
        W1_2, 1024L * 2048L,
        b1_2,
        out, 64L, 32768L, 2048L,
        out, 1024, 2048);

    (void)in_sizes; (void)n_in; (void)out_size;
}

// round 11
// speedup vs baseline: 1.3056x; 1.0000x over previous
#include <cuda_runtime.h>
#include <cstdint>

// ---------------- problem constants ----------------
// B=256, D0=16, D1=32, D2=64, D_FFN=2048, F1=2048, F2=1024
// out dtype float32, out_size = 256*16*32*64 = 8388608

#define BM 128
#define BN 128
#define BK 32
#define BKP 36          // padded smem row stride (floats) -> conflict-free frags
#define STAGES 3
#define NTHREADS 256

// scratch: h1 [B, D0, 2048] (32MB), h2 [B, D1, 2048] (64MB)
__device__ __align__(128) float g_h1[256L * 16 * 2048];
__device__ __align__(128) float g_h2[256L * 32 * 2048];

static __device__ __forceinline__ uint32_t smem_u32(const void* p) {
    return (uint32_t)__cvta_generic_to_shared(p);
}
static __device__ __forceinline__ void cp_async16(uint32_t s, const void* g) {
    asm volatile("cp.async.cg.shared.global [%0], [%1], 16;\n" :: "r"(s), "l"(g));
}
static __device__ __forceinline__ void cp_commit() {
    asm volatile("cp.async.commit_group;\n" ::: "memory");
}
template <int N_>
static __device__ __forceinline__ void cp_wait() {
    asm volatile("cp.async.wait_group %0;\n" :: "n"(N_) : "memory");
}
// NOTE: no cvt.rna.tf32 — HMMA.tf32 reads bits[31:13] of the operand register,
// so raw fp32 bits act as round-toward-zero tf32 (CUTLASS fast path).
static __device__ __forceinline__ void mma_tf32(float c[4],
                                                uint32_t a0, uint32_t a1, uint32_t a2, uint32_t a3,
                                                uint32_t b0, uint32_t b1) {
    asm volatile(
        "mma.sync.aligned.m16n8k8.row.col.f32.tf32.tf32.f32 "
        "{%0,%1,%2,%3}, {%4,%5,%6,%7}, {%8,%9}, {%0,%1,%2,%3};\n"
        : "+f"(c[0]), "+f"(c[1]), "+f"(c[2]), "+f"(c[3])
        : "r"(a0), "r"(a1), "r"(a2), "r"(a3), "r"(b0), "r"(b1));
}

// Grouped TN GEMM:  C[m,n] = sum_k A_g[m,k] * W_g[n,k]
// A addressing (handles strided gather without a transpose pass):
//   A elem (m,k)  at A0 + g*a_g + m*a_ldr + (k>>6)*a_ldblk + (k&63)
// W addressing:   W0 + g*w_g + n*K + k            (always K-contiguous)
// out addressing: out0 + g*o_g + m*o_ldr + (n>>6)*o_ldblk + (n&63)
// MODE 0: out = gelu(acc + bias[n])
// MODE 1: out = aux0[same index] + 0.5f*(acc + bias[n])
template <int MODE>
__global__ void __launch_bounds__(NTHREADS, 2)
grouped_gemm(const float* __restrict__ A0, long a_g, long a_ldr, long a_ldblk,
             const float* __restrict__ W0, long w_g,
             const float* __restrict__ bias0,
             float* __restrict__ out0, long o_g, long o_ldr, long o_ldblk,
             const float* __restrict__ aux0,
             int N, int K) {
    extern __shared__ float smem[];
    float* As = smem;                        // [STAGES][BM][BKP]
    float* Bs = smem + (long)STAGES * BM * BKP;  // [STAGES][BN][BKP]

    const int g  = blockIdx.z;
    const int bm = blockIdx.y;
    const int bn = blockIdx.x;

    const float* A    = A0 + (long)g * a_g;
    const float* W    = W0 + (long)g * w_g;
    const float* bias = bias0 + (long)g * (long)N;

    const int tid  = threadIdx.x;
    const int lrow = tid >> 3;            // 0..31 (row within a 32-row pass)
    const int lk4  = (tid & 7) * 4;       // 0,4,...,28 (k offset of 16B chunk)

    const int warp = tid >> 5;
    const int lane = tid & 31;
    const int wm   = (warp >> 2) * 64;    // warp m offset (0 / 64)
    const int wn   = (warp & 3) * 32;     // warp n offset (0/32/64/96)
    const int qrow = lane >> 2;           // 0..7
    const int qk   = lane & 3;            // 0..3

    float c[4][4][4];
#pragma unroll
    for (int mi = 0; mi < 4; mi++)
#pragma unroll
        for (int ni = 0; ni < 4; ni++)
#pragma unroll
            for (int r = 0; r < 4; r++) c[mi][ni][r] = 0.0f;

    auto load_tile = [&](int kt, int stage) {
        float* as = As + (long)stage * BM * BKP;
        float* bs = Bs + (long)stage * BN * BKP;
        const long kg   = (long)kt * BK + lk4;
        const long ablk = (kg >> 6) * a_ldblk + (kg & 63);
#pragma unroll
        for (int p = 0; p < 4; p++) {
            const int r = lrow + p * 32;
            cp_async16(smem_u32(&as[r * BKP + lk4]),
                       A + (long)(bm * BM + r) * a_ldr + ablk);
        }
#pragma unroll
        for (int p = 0; p < 4; p++) {
            const int r = lrow + p * 32;
            cp_async16(smem_u32(&bs[r * BKP + lk4]),
                       W + (long)(bn * BN + r) * K + kg);
        }
    };

    const int KT = K / BK;

    // prologue: prefetch STAGES-1 tiles
#pragma unroll
    for (int s = 0; s < STAGES - 1; s++) {
        load_tile(s, s);
        cp_commit();
    }

    for (int kt = 0; kt < KT; kt++) {
        cp_wait<STAGES - 2>();
        __syncthreads();   // also protects the stage about to be overwritten

        const int nt = kt + STAGES - 1;
        if (nt < KT) load_tile(nt, nt % STAGES);
        cp_commit();

        // read fragments as raw bits (no cvt; tf32 HMMA ignores low 13 bits)
        const uint32_t* as = (const uint32_t*)(As + (long)(kt % STAGES) * BM * BKP);
        const uint32_t* bs = (const uint32_t*)(Bs + (long)(kt % STAGES) * BN * BKP);

#pragma unroll
        for (int ks = 0; ks < BK / 8; ks++) {
            const int k0 = ks * 8 + qk;
            uint32_t af[4][4], bf[4][2];
#pragma unroll
            for (int mi = 0; mi < 4; mi++) {
                const int m = wm + mi * 16 + qrow;
                af[mi][0] = as[m * BKP + k0];
                af[mi][1] = as[(m + 8) * BKP + k0];
                af[mi][2] = as[m * BKP + k0 + 4];
                af[mi][3] = as[(m + 8) * BKP + k0 + 4];
            }
#pragma unroll
            for (int ni = 0; ni < 4; ni++) {
                const int n = wn + ni * 8 + qrow;
                bf[ni][0] = bs[n * BKP + k0];
                bf[ni][1] = bs[n * BKP + k0 + 4];
            }
#pragma unroll
            for (int mi = 0; mi < 4; mi++)
#pragma unroll
                for (int ni = 0; ni < 4; ni++)
                    mma_tf32(c[mi][ni], af[mi][0], af[mi][1], af[mi][2], af[mi][3],
                             bf[ni][0], bf[ni][1]);
        }
    }
    cp_wait<0>();

    // -------- epilogue --------
    const long og = (long)g * o_g;
#pragma unroll
    for (int mi = 0; mi < 4; mi++) {
        const int mrow = bm * BM + wm + mi * 16 + qrow;
#pragma unroll
        for (int ni = 0; ni < 4; ni++) {
            const int ncol = bn * BN + wn + ni * 8 + qk * 2;
#pragma unroll
            for (int rr = 0; rr < 2; rr++) {
                const long mterm = (long)(mrow + rr * 8) * o_ldr;
#pragma unroll
                for (int cc = 0; cc < 2; cc++) {
                    const int n_g = ncol + cc;
                    const float v = c[mi][ni][rr * 2 + cc] + bias[n_g];
                    const long oaddr = og + mterm + (long)(n_g >> 6) * o_ldblk + (n_g & 63);
                    if (MODE == 0) {
                        // exact-erf GELU
                        out0[oaddr] = 0.5f * v * (1.0f + erff(v * 0.70710678118654752f));
                    } else {
                        out0[oaddr] = aux0[oaddr] + 0.5f * v;
                    }
                }
            }
        }
    }
}

extern "C" void kernel_launch(void* const* d_in, const int* in_sizes, int n_in,
                              void* d_out, int out_size) {
    const float* x    = (const float*)d_in[0];
    const float* W0_1 = (const float*)d_in[1];
    const float* b0_1 = (const float*)d_in[2];
    const float* W1_1 = (const float*)d_in[3];
    const float* b1_1 = (const float*)d_in[4];
    const float* W0_2 = (const float*)d_in[5];
    const float* b0_2 = (const float*)d_in[6];
    const float* W1_2 = (const float*)d_in[7];
    const float* b1_2 = (const float*)d_in[8];
    float* out = (float*)d_out;

    void* p1 = nullptr; void* p2 = nullptr;
    cudaGetSymbolAddress(&p1, g_h1);
    cudaGetSymbolAddress(&p2, g_h2);
    float* h1 = (float*)p1;
    float* h2 = (float*)p2;

    const size_t shm = (size_t)STAGES * (BM + BN) * BKP * sizeof(float);  // 110592
    cudaFuncSetAttribute(grouped_gemm<0>, cudaFuncAttributeMaxDynamicSharedMemorySize, (int)shm);
    cudaFuncSetAttribute(grouped_gemm<1>, cudaFuncAttributeMaxDynamicSharedMemorySize, (int)shm);

    dim3 blk(NTHREADS);

    // G1a: h1[b,i,k] = gelu(x1 @ W0_1[i]^T + b0_1[i])    M=256,N=2048,K=2048, G=16
    grouped_gemm<0><<<dim3(2048 / BN, 256 / BM, 16), blk, shm>>>(
        x, 2048L, 32768L, 64L,
        W0_1, 2048L * 2048L,
        b0_1,
        h1, 2048L, 32768L, 64L,
        nullptr, 2048, 2048);

    // G2a: h2[b,j,k] = gelu(x2 @ W0_2[j]^T + b0_2[j])    M=256,N=2048,K=1024, G=32
    // A gather: x2[b, i*64+d] = x[b,i,j,d] -> base x + j*64, ldr 32768, ldblk 2048
    grouped_gemm<0><<<dim3(2048 / BN, 256 / BM, 32), blk, shm>>>(
        x, 64L, 32768L, 2048L,
        W0_2, 2048L * 1024L,
        b0_2,
        h2, 2048L, 65536L, 64L,
        nullptr, 2048, 1024);

    // G1b: out[b,i,f1] = x[b,i,f1] + 0.5*(h1 @ W1_1[i]^T + b1_1[i])   N=2048,K=2048, G=16
    grouped_gemm<1><<<dim3(2048 / BN, 256 / BM, 16), blk, shm>>>(
        h1, 2048L, 32768L, 64L,
        W1_1, 2048L * 2048L,
        b1_1,
        out, 2048L, 32768L, 64L,
        x, 2048, 2048);

    // G2b: out[b,i,j,d] += 0.5*(h2 @ W1_2[j]^T + b1_2[j])   N=1024,K=2048, G=32
    // out scatter: n=(i,d) -> base out + j*64, ldr 32768, ldblk 2048; aux = out (read-modify-write)
    grouped_gemm<1><<<dim3(1024 / BN, 256 / BM, 32), blk, shm>>>(
        h2, 2048L, 65536L, 64L,
        W1_2, 1024L * 2048L,
        b1_2,
        out, 64L, 32768L, 2048L,
        out, 1024, 2048);

    (void)in_sizes; (void)n_in; (void)out_size;
}